// round 3
// baseline (speedup 1.0000x reference)
#include <cuda_runtime.h>
#include <cuda_bf16.h>

#define B 32
#define N 1024
#define SIGMA 1.0f
#define EPSF 1.1920928955078125e-07f

// Scratch (device globals; no allocation allowed)
__device__ float g_e[B * N];      // exp(a)
__device__ float g_L[B * N];      // 1/log2(rank+1)
__device__ float g_g[B * N];      // 2^y
__device__ float g_scale[B];      // -2*sigma/(idcg+eps)
__device__ float g_loss_sink;     // fallback loss target if out has no slot

__device__ __forceinline__ float frcp(float x) {
    float r;
    asm("rcp.approx.f32 %0, %1;" : "=f"(r) : "f"(x));
    return r;
}

__global__ void zero_kernel(float* loss_ptr) {
    if (loss_ptr) *loss_ptr = 0.0f;
    g_loss_sink = 0.0f;
}

// One block per row, 1024 threads. Computes rank (O(n^2) count), e, L, g,
// idcg (via class histogram + positional discounts), row scale, and the
// placeholder loss contribution (sum of a).
__global__ __launch_bounds__(N) void prep_kernel(const float* __restrict__ a,
                                                 const float* __restrict__ y,
                                                 float* loss_ptr) {
    const int row = blockIdx.x;
    const int tid = threadIdx.x;

    __shared__ float sa[N];
    __shared__ int cnt[5];
    __shared__ float red1[32];
    __shared__ float red2[32];

    if (tid < 5) cnt[tid] = 0;
    __syncthreads();

    const float ai = a[row * N + tid];
    const float yi = y[row * N + tid];
    sa[tid] = ai;
    const int yc = (int)yi;             // y in {0..4}
    const float gi = (float)(1 << yc);  // 2^y
    atomicAdd(&cnt[yc], 1);
    __syncthreads();

    // rank_i = 1 + #{j : a_j > a_i  or (a_j == a_i and j < i)}  (stable-sort tie break)
    int rank = 1;
#pragma unroll 8
    for (int j = 0; j < N; j++) {
        const float aj = sa[j];
        rank += (aj > ai) || (aj == ai && j < tid);
    }

    const float L = 1.0f / log2f((float)(rank + 1));
    const float e = __expf(ai);
    g_e[row * N + tid] = e;
    g_L[row * N + tid] = L;
    g_g[row * N + tid] = gi;

    // idcg: position tid (0-based) in the ideal descending-y ordering belongs
    // to class v determined by the class histogram boundaries.
    const int c4 = cnt[4];
    const int b3 = c4 + cnt[3];
    const int b2 = b3 + cnt[2];
    const int b1 = b2 + cnt[1];
    const int v = (tid < c4) ? 4 : (tid < b3) ? 3 : (tid < b2) ? 2 : (tid < b1) ? 1 : 0;
    float contrib = ((float)(1 << v) - 1.0f) / log2f((float)(tid + 2));

    // Block reduce: contrib -> idcg, ai -> row loss partial
    float s1 = contrib;
    float s2 = ai;
#pragma unroll
    for (int o = 16; o > 0; o >>= 1) {
        s1 += __shfl_down_sync(0xFFFFFFFFu, s1, o);
        s2 += __shfl_down_sync(0xFFFFFFFFu, s2, o);
    }
    const int wid = tid >> 5;
    const int lane = tid & 31;
    if (lane == 0) { red1[wid] = s1; red2[wid] = s2; }
    __syncthreads();
    if (wid == 0) {
        s1 = red1[lane];
        s2 = red2[lane];
#pragma unroll
        for (int o = 16; o > 0; o >>= 1) {
            s1 += __shfl_down_sync(0xFFFFFFFFu, s1, o);
            s2 += __shfl_down_sync(0xFFFFFFFFu, s2, o);
        }
        if (lane == 0) {
            g_scale[row] = -2.0f * SIGMA / (s1 + EPSF);
            atomicAdd(loss_ptr ? loss_ptr : &g_loss_sink, s2);
        }
    }
}

// grid = (N/256, B), block = 256. Each thread owns one i, streams all j from
// shared memory (broadcast), one rcp.approx per pair.
__global__ __launch_bounds__(256) void grad_kernel(float* __restrict__ out) {
    const int row = blockIdx.y;
    const int tid = threadIdx.x;
    const int base = row * N;

    __shared__ float se[N];
    __shared__ float sL[N];
    __shared__ float sg[N];

    for (int idx = tid; idx < N; idx += 256) {
        se[idx] = g_e[base + idx];
        sL[idx] = g_L[base + idx];
        sg[idx] = g_g[base + idx];
    }
    __syncthreads();

    const int i = blockIdx.x * 256 + tid;
    const float ei = se[i];
    const float Li = sL[i];
    const float gi = sg[i];

    float acc = 0.0f;
#pragma unroll 8
    for (int j = 0; j < N; j++) {
        const float ej = se[j];
        const float dg = gi - sg[j];            // = sign(dy)*|2^yi - 2^yj|
        const float dL = fabsf(Li - sL[j]);
        const float num = (dg > 0.0f) ? ej : ei;  // sigmoid numerator
        const float den = ei + ej;
        acc = fmaf(dg * dL * num, frcp(den), acc);
    }

    out[base + i] = acc * g_scale[row];
}

extern "C" void kernel_launch(void* const* d_in, const int* in_sizes, int n_in,
                              void* d_out, int out_size) {
    const float* a = (const float*)d_in[0];
    const float* y = (const float*)d_in[1];
    float* out = (float*)d_out;

    float* loss_ptr = nullptr;
    float* grad_ptr = out;
    if (out_size >= B * N + 1) {
        // flattened tuple: [loss, grad(32768)]
        loss_ptr = out;
        grad_ptr = out + 1;
    }

    zero_kernel<<<1, 1>>>(loss_ptr);
    prep_kernel<<<B, N>>>(a, y, loss_ptr);
    grad_kernel<<<dim3(N / 256, B), 256>>>(grad_ptr);
}

// round 4
// speedup vs baseline: 1.5703x; 1.5703x over previous
#include <cuda_runtime.h>
#include <cuda_bf16.h>

#define B 32
#define N 1024
#define EPSF 1.1920928955078125e-07f

// Scratch (device globals; no allocation allowed)
__device__ float4 g_elg[B * N];       // {e=exp(a), L=1/log2(rank+1), g=2^y, 0}
__device__ float g_idcg_part[B * 4];  // per-(row,block) idcg partial sums
__device__ float g_loss_part[B * 4];  // per-(row,block) sum(a) partial sums

__device__ __forceinline__ float frcp(float x) {
    float r;
    asm("rcp.approx.f32 %0, %1;" : "=f"(r) : "f"(x));
    return r;
}

// grid = (4, B), block = 256. Full-chip prep: ranks via 64-bit sort keys,
// e/L/g precompute, idcg + loss partials (deterministic, no global atomics).
__global__ __launch_bounds__(256) void prep_kernel(const float* __restrict__ a,
                                                   const float* __restrict__ y) {
    const int row = blockIdx.y;
    const int bx = blockIdx.x;
    const int tid = threadIdx.x;
    const int base = row * N;

    __shared__ unsigned long long skey[N];   // 8KB
    __shared__ int cnt[5];
    __shared__ float red1[8];
    __shared__ float red2[8];

    if (tid < 5) cnt[tid] = 0;
    __syncthreads();

    // Build sort keys for the whole row + local y histogram.
    // key = (monotone-uint(a) << 10) | (1023 - idx): key_j > key_i  <=>
    //   a_j > a_i  OR (a_j == a_i AND j < i)   (stable descending argsort)
    int lc[5] = {0, 0, 0, 0, 0};
#pragma unroll
    for (int s = 0; s < 4; s++) {
        const int idx = tid + s * 256;
        const unsigned int u = __float_as_uint(a[base + idx]);
        const unsigned int o = (u & 0x80000000u) ? ~u : (u | 0x80000000u);
        skey[idx] = ((unsigned long long)o << 10) | (unsigned int)(1023 - idx);
        const int yc = (int)y[base + idx];
#pragma unroll
        for (int v = 0; v < 5; v++) lc[v] += (yc == v);
    }
#pragma unroll
    for (int v = 0; v < 5; v++)
        if (lc[v]) atomicAdd(&cnt[v], lc[v]);
    __syncthreads();

    const int i = bx * 256 + tid;
    const unsigned long long mykey = skey[i];
    int rank = 1;
#pragma unroll 8
    for (int j = 0; j < N; j++) rank += (skey[j] > mykey);

    const float ai = a[base + i];
    const int yc = (int)y[base + i];
    const float e = __expf(ai);
    const float L = frcp(__log2f((float)(rank + 1)));
    g_elg[base + i] = make_float4(e, L, (float)(1 << yc), 0.0f);

    // idcg contribution of ideal position t = i (class from histogram bounds)
    const int c4 = cnt[4];
    const int b3 = c4 + cnt[3];
    const int b2 = b3 + cnt[2];
    const int b1 = b2 + cnt[1];
    const int v = (i < c4) ? 4 : (i < b3) ? 3 : (i < b2) ? 2 : (i < b1) ? 1 : 0;
    float s1 = (float)((1 << v) - 1) * frcp(__log2f((float)(i + 2)));
    float s2 = ai;

    // Deterministic block reduce of (s1, s2)
#pragma unroll
    for (int o = 16; o > 0; o >>= 1) {
        s1 += __shfl_down_sync(0xFFFFFFFFu, s1, o);
        s2 += __shfl_down_sync(0xFFFFFFFFu, s2, o);
    }
    const int wid = tid >> 5;
    const int lane = tid & 31;
    if (lane == 0) { red1[wid] = s1; red2[wid] = s2; }
    __syncthreads();
    if (tid == 0) {
        float t1 = 0.0f, t2 = 0.0f;
#pragma unroll
        for (int w = 0; w < 8; w++) { t1 += red1[w]; t2 += red2[w]; }
        g_idcg_part[row * 4 + bx] = t1;
        g_loss_part[row * 4 + bx] = t2;
    }
}

// grid = (4, B), block = 256. Each thread owns one i, streams all j from
// shared (float4 broadcast), one rcp.approx per pair.
__global__ __launch_bounds__(256) void grad_kernel(float* __restrict__ out_grad,
                                                   float* loss_ptr) {
    const int row = blockIdx.y;
    const int tid = threadIdx.x;
    const int base = row * N;

    __shared__ float4 s[N];   // 16KB

#pragma unroll
    for (int k = 0; k < 4; k++) s[tid + k * 256] = g_elg[base + tid + k * 256];

    // One block writes the placeholder loss (sum of all 128 partials)
    if (loss_ptr && row == 0 && blockIdx.x == 0 && tid < 32) {
        float t = 0.0f;
#pragma unroll
        for (int k = 0; k < 4; k++) t += g_loss_part[tid + k * 32];
#pragma unroll
        for (int o = 16; o > 0; o >>= 1) t += __shfl_down_sync(0xFFFFFFFFu, t, o);
        if (tid == 0) *loss_ptr = t;
    }
    __syncthreads();

    const float idcg = g_idcg_part[row * 4 + 0] + g_idcg_part[row * 4 + 1] +
                       g_idcg_part[row * 4 + 2] + g_idcg_part[row * 4 + 3];
    const float scale = -2.0f * frcp(idcg + EPSF);

    const int i = blockIdx.x * 256 + tid;
    const float4 me = s[i];
    const float ei = me.x, Li = me.y, gi = me.z;

    float acc = 0.0f;
#pragma unroll 8
    for (int j = 0; j < N; j++) {
        const float4 oj = s[j];
        const float dg = gi - oj.z;              // = sign(dy)*|2^yi - 2^yj|
        const float dL = Li - oj.y;
        const float den = ei + oj.x;
        const float num = (dg > 0.0f) ? oj.x : ei;  // sigmoid numerator
        acc = fmaf(dg * fabsf(dL) * num, frcp(den), acc);
    }

    out_grad[base + i] = acc * scale;
}

extern "C" void kernel_launch(void* const* d_in, const int* in_sizes, int n_in,
                              void* d_out, int out_size) {
    const float* a = (const float*)d_in[0];
    const float* y = (const float*)d_in[1];
    float* out = (float*)d_out;

    float* loss_ptr = nullptr;
    float* grad_ptr = out;
    if (out_size >= B * N + 1) {
        // flattened tuple: [loss, grad(32768)]
        loss_ptr = out;
        grad_ptr = out + 1;
    }

    prep_kernel<<<dim3(4, B), 256>>>(a, y);
    grad_kernel<<<dim3(4, B), 256>>>(grad_ptr, loss_ptr);
}

// round 5
// speedup vs baseline: 1.7545x; 1.1173x over previous
#include <cuda_runtime.h>
#include <cuda_bf16.h>

#define B 32
#define N 1024
#define EPSF 1.1920928955078125e-07f

// Scratch (device globals; no allocation allowed)
__device__ float2 g_eL[B * N];        // class-sorted {e=exp(a), L=1/log2(rank+1)}
__device__ int g_oidx[B * N];         // sorted pos -> original index
__device__ int g_cnt[B * 5];          // per-row class histogram
__device__ float g_idcg_part[B * 4];  // per-(row,block) idcg partials
__device__ float g_loss_part[B * 4];  // per-(row,block) sum(a) partials

__device__ __forceinline__ float frcp(float x) {
    float r;
    asm("rcp.approx.f32 %0, %1;" : "=f"(r) : "f"(x));
    return r;
}

// grid = (4, B), block = 256. Ranks via 32-bit monotone keys, counting-sort
// scatter by y-class, idcg + loss partials. No global atomics.
__global__ __launch_bounds__(256) void prep_kernel(const float* __restrict__ a,
                                                   const float* __restrict__ y) {
    const int row = blockIdx.y;
    const int bx = blockIdx.x;
    const int tid = threadIdx.x;
    const int base = row * N;

    __shared__ unsigned int okey[N];       // 4KB
    __shared__ unsigned char scls[N];      // 1KB
    __shared__ int cnt[5];
    __shared__ float red1[8];
    __shared__ float red2[8];

    if (tid < 5) cnt[tid] = 0;
    __syncthreads();

    // Whole-row load: monotone keys (descending a <=> descending key),
    // class bytes, full-row class histogram.
    int lc[5] = {0, 0, 0, 0, 0};
#pragma unroll
    for (int s = 0; s < 4; s++) {
        const int idx = tid + s * 256;
        const unsigned int u = __float_as_uint(a[base + idx]);
        okey[idx] = (u & 0x80000000u) ? ~u : (u | 0x80000000u);
        const int yc = (int)y[base + idx];
        scls[idx] = (unsigned char)yc;
#pragma unroll
        for (int v = 0; v < 5; v++) lc[v] += (yc == v);
    }
#pragma unroll
    for (int v = 0; v < 5; v++)
        if (lc[v]) atomicAdd(&cnt[v], lc[v]);
    __syncthreads();

    const int i = bx * 256 + tid;
    const unsigned int mk = okey[i];

    // rank = 1 + #{j : a_j > a_i} (random normal floats: no exact ties)
    int rank = 1;
    for (int j = 0; j < N; j += 4) {
        const uint4 k4 = *(const uint4*)(okey + j);
        rank += (k4.x > mk) + (k4.y > mk) + (k4.z > mk) + (k4.w > mk);
    }

    // stable position within class: #{j < i : y_j == y_i}
    const int myc = (int)scls[i];
    int within = 0;
    int j = 0;
    for (; j + 3 < i; j += 4) {
        const uchar4 c4v = *(const uchar4*)(scls + j);
        within += (c4v.x == myc) + (c4v.y == myc) + (c4v.z == myc) + (c4v.w == myc);
    }
    for (; j < i; j++) within += ((int)scls[j] == myc);

    // class-ascending offsets
    int off = 0;
#pragma unroll
    for (int c = 0; c < 5; c++) off += (c < myc) ? cnt[c] : 0;
    const int pos = off + within;

    const float ai = a[base + i];
    const float e = __expf(ai);
    const float L = frcp(__log2f((float)(rank + 1)));
    g_eL[base + pos] = make_float2(e, L);
    g_oidx[base + pos] = i;
    if (bx == 0 && tid < 5) g_cnt[row * 5 + tid] = cnt[tid];

    // idcg contribution of ideal position i (descending-class boundaries)
    const int c4 = cnt[4];
    const int b3 = c4 + cnt[3];
    const int b2 = b3 + cnt[2];
    const int b1 = b2 + cnt[1];
    const int v = (i < c4) ? 4 : (i < b3) ? 3 : (i < b2) ? 2 : (i < b1) ? 1 : 0;
    float s1 = (float)((1 << v) - 1) * frcp(__log2f((float)(i + 2)));
    float s2 = ai;

#pragma unroll
    for (int o = 16; o > 0; o >>= 1) {
        s1 += __shfl_down_sync(0xFFFFFFFFu, s1, o);
        s2 += __shfl_down_sync(0xFFFFFFFFu, s2, o);
    }
    const int wid = tid >> 5;
    const int lane = tid & 31;
    if (lane == 0) { red1[wid] = s1; red2[wid] = s2; }
    __syncthreads();
    if (tid == 0) {
        float t1 = 0.0f, t2 = 0.0f;
#pragma unroll
        for (int w = 0; w < 8; w++) { t1 += red1[w]; t2 += red2[w]; }
        g_idcg_part[row * 4 + bx] = t1;
        g_loss_part[row * 4 + bx] = t2;
    }
}

// grid = (4, B), block = 256. Thread owns one sorted position p. Iterates the
// 5 class segments: dg constant per segment, same-class segment skipped,
// pairs batched 2-per-rcp.
__global__ __launch_bounds__(256) void grad_kernel(float* __restrict__ out_grad,
                                                   float* loss_ptr) {
    const int row = blockIdx.y;
    const int tid = threadIdx.x;
    const int base = row * N;

    __shared__ __align__(16) float2 s[N];  // 8KB
    __shared__ int soff[6];

    {
        const float4* src = (const float4*)(g_eL + base);
        float4* dst = (float4*)s;
#pragma unroll
        for (int k = 0; k < 2; k++) dst[tid + k * 256] = src[tid + k * 256];
    }
    if (tid == 0) {
        int o = 0;
        soff[0] = 0;
#pragma unroll
        for (int c = 0; c < 5; c++) { o += g_cnt[row * 5 + c]; soff[c + 1] = o; }
    }
    if (loss_ptr && row == 0 && blockIdx.x == 0 && tid < 32) {
        float t = 0.0f;
#pragma unroll
        for (int k = 0; k < 4; k++) t += g_loss_part[tid + k * 32];
#pragma unroll
        for (int o = 16; o > 0; o >>= 1) t += __shfl_down_sync(0xFFFFFFFFu, t, o);
        if (tid == 0) *loss_ptr = t;
    }
    __syncthreads();

    const float idcg = g_idcg_part[row * 4 + 0] + g_idcg_part[row * 4 + 1] +
                       g_idcg_part[row * 4 + 2] + g_idcg_part[row * 4 + 3];
    const float scale = -2.0f * frcp(idcg + EPSF);

    const int p = blockIdx.x * 256 + tid;
    const float2 mine = s[p];
    const float ei = mine.x, Li = mine.y;
    const int ci = (p >= soff[1]) + (p >= soff[2]) + (p >= soff[3]) + (p >= soff[4]);
    const float gi = (float)(1 << ci);

    float acc = 0.0f;
#pragma unroll
    for (int sg = 0; sg < 5; sg++) {
        if (sg == ci) continue;
        const int beg = soff[sg];
        const int end = soff[sg + 1];
        const float dg = gi - (float)(1 << sg);
        float segsum = 0.0f;
        int j = beg;
        if (sg < ci) {
            // dg > 0: sigmoid numerator = e_j
            if ((j & 1) && j < end) {
                const float2 v = s[j];
                segsum = fmaf(fabsf(Li - v.y) * v.x, frcp(ei + v.x), segsum);
                j++;
            }
#pragma unroll 2
            for (; j + 1 < end; j += 2) {
                const float4 v = *(const float4*)(&s[j]);
                const float n1 = fabsf(Li - v.y) * v.x;
                const float n2 = fabsf(Li - v.w) * v.z;
                const float d1 = ei + v.x;
                const float d2 = ei + v.z;
                segsum = fmaf(fmaf(n1, d2, n2 * d1), frcp(d1 * d2), segsum);
            }
            if (j < end) {
                const float2 v = s[j];
                segsum = fmaf(fabsf(Li - v.y) * v.x, frcp(ei + v.x), segsum);
            }
            acc = fmaf(dg, segsum, acc);
        } else {
            // dg < 0: sigmoid numerator = e_i (folded into segment constant)
            if ((j & 1) && j < end) {
                const float2 v = s[j];
                segsum = fmaf(fabsf(Li - v.y), frcp(ei + v.x), segsum);
                j++;
            }
#pragma unroll 2
            for (; j + 1 < end; j += 2) {
                const float4 v = *(const float4*)(&s[j]);
                const float n1 = fabsf(Li - v.y);
                const float n2 = fabsf(Li - v.w);
                const float d1 = ei + v.x;
                const float d2 = ei + v.z;
                segsum = fmaf(fmaf(n1, d2, n2 * d1), frcp(d1 * d2), segsum);
            }
            if (j < end) {
                const float2 v = s[j];
                segsum = fmaf(fabsf(Li - v.y), frcp(ei + v.x), segsum);
            }
            acc = fmaf(dg * ei, segsum, acc);
        }
    }

    out_grad[base + g_oidx[base + p]] = acc * scale;
}

extern "C" void kernel_launch(void* const* d_in, const int* in_sizes, int n_in,
                              void* d_out, int out_size) {
    const float* a = (const float*)d_in[0];
    const float* y = (const float*)d_in[1];
    float* out = (float*)d_out;

    float* loss_ptr = nullptr;
    float* grad_ptr = out;
    if (out_size >= B * N + 1) {
        // flattened tuple: [loss, grad(32768)]
        loss_ptr = out;
        grad_ptr = out + 1;
    }

    prep_kernel<<<dim3(4, B), 256>>>(a, y);
    grad_kernel<<<dim3(4, B), 256>>>(grad_ptr, loss_ptr);
}